// round 3
// baseline (speedup 1.0000x reference)
#include <cuda_runtime.h>
#include <cuda_bf16.h>

// RKN scan R3: 512 threads/CTA, 4-way diagonal split, smem-carried state,
// lane-parallel softmax, bf16 off-diagonal tm planes (fp32 diagonal).

#define NB   128
#define NT   128
#define NLOD 128
#define NK   16

// ---- dynamic smem layout (byte offsets) ----
static constexpr int OD_OFF    = 0;                       // 3 planes uint4[NK*NLOD]
static constexpr int OD_BYTES  = 3 * NK * NLOD * 16;      // 98304
static constexpr int DG_OFF    = OD_OFF + OD_BYTES;       // float4[NK*NLOD]
static constexpr int DG_BYTES  = NK * NLOD * 16;          // 32768
static constexpr int STATE_LEN = 136;
static constexpr int S_MU      = DG_OFF + DG_BYTES;
static constexpr int S_ML      = S_MU + STATE_LEN * 4;
static constexpr int S_CU      = S_ML + STATE_LEN * 4;
static constexpr int S_CL      = S_CU + STATE_LEN * 4;
static constexpr int S_CS      = S_CL + STATE_LEN * 4;
static constexpr int S_RED     = S_CS + STATE_LEN * 4;    // 64 floats
static constexpr int S_PART4   = S_RED + 256;             // float4[4*128]
static constexpr int S_PART1   = S_PART4 + 4 * 128 * 16;  // float[4*128]
static constexpr int SMEM_BYTES = S_PART1 + 4 * 128 * 4;  // ~144.5 KB

__device__ __forceinline__ unsigned int pk(float a, float b) {
    __nv_bfloat162 t = __floats2bfloat162_rn(a, b);
    return reinterpret_cast<unsigned int&>(t);
}
__device__ __forceinline__ unsigned long long bf2f2(unsigned int p) {
    unsigned long long r;
    asm("{\n\t.reg .b32 l,h;\n\t"
        "shl.b32 l, %1, 16;\n\t"
        "and.b32 h, %1, 0xFFFF0000;\n\t"
        "mov.b64 %0, {l,h};\n\t}" : "=l"(r) : "r"(p));
    return r;
}
__device__ __forceinline__ void ffma2(unsigned long long& acc,
                                      unsigned long long x,
                                      unsigned long long a2) {
    asm("fma.rn.f32x2 %0, %1, %2, %0;" : "+l"(acc) : "l"(x), "l"(a2));
}
__device__ __forceinline__ unsigned long long dup2(float a) {
    unsigned long long r;
    asm("mov.b64 %0, {%1, %1};" : "=l"(r) : "f"(a));
    return r;
}
__device__ __forceinline__ void unpk2(unsigned long long r, float& x, float& y) {
    asm("mov.b64 {%0, %1}, %2;" : "=f"(x), "=f"(y) : "l"(r));
}

#define RED_ROUND(m)                                                          \
  _Pragma("unroll")                                                           \
  for (int k = 0; k < (m); k++) {                                             \
    float a_ = v[k], c_ = v[k + (m)];                                         \
    bool  hi_ = (lane & (m)) != 0;                                            \
    float keep_ = hi_ ? c_ : a_;                                              \
    float send_ = hi_ ? a_ : c_;                                              \
    v[k] = keep_ + __shfl_xor_sync(0xffffffffu, send_, (m));                  \
  }

#define BAND_ACC(d, a11, a12, a21, a22)                                       \
  {                                                                           \
    int j_ = i + (d);                                                         \
    float muj = s_mu[j_], mlj = s_ml[j_];                                     \
    float cuj = s_cu[j_], clj = s_cl[j_], csj = s_cs[j_];                     \
    nmu = fmaf((a11), muj, nmu); nmu = fmaf((a12), mlj, nmu);                 \
    nml = fmaf((a21), muj, nml); nml = fmaf((a22), mlj, nml);                 \
    ncu = fmaf((a11) * (a11), cuj, ncu);                                      \
    ncu = fmaf(2.0f * (a11) * (a12), csj, ncu);                               \
    ncu = fmaf((a12) * (a12), clj, ncu);                                      \
    ncl = fmaf((a21) * (a21), cuj, ncl);                                      \
    ncl = fmaf(2.0f * (a21) * (a22), csj, ncl);                               \
    ncl = fmaf((a22) * (a22), clj, ncl);                                      \
    ncs = fmaf((a21) * (a11), cuj, ncs);                                      \
    ncs = fmaf(fmaf((a22), (a11), (a21) * (a12)), csj, ncs);                  \
    ncs = fmaf((a22) * (a12), clj, ncs);                                      \
  }

__global__ void __launch_bounds__(512, 1)
rkn_kernel(const float* __restrict__ lobs,   // (B,T,LOD)
           const float* __restrict__ ovars,  // (B,T,LOD)
           const float* __restrict__ imean,  // (B,2*LOD)
           const float* __restrict__ icu,
           const float* __restrict__ icl,
           const float* __restrict__ ics,
           const float* __restrict__ tm11,   // (K,LOD,LOD)
           const float* __restrict__ tm12,
           const float* __restrict__ tm21,
           const float* __restrict__ tm22,
           const float* __restrict__ cw,     // (2*LOD, K)
           const float* __restrict__ cb,     // (K,)
           const float* __restrict__ tcu,
           const float* __restrict__ tcl,
           float* __restrict__ out)
{
    extern __shared__ char smraw[];
    const int b    = blockIdx.x;
    const int tid  = threadIdx.x;
    const int lane = tid & 31;
    const int warp = tid >> 5;
    const int i    = tid & 127;   // row
    const int g    = tid >> 7;    // diagonal group 0..3

    uint4*  od   = reinterpret_cast<uint4*>(smraw + OD_OFF);
    float4* dg   = reinterpret_cast<float4*>(smraw + DG_OFF);
    float*  s_mu = reinterpret_cast<float*>(smraw + S_MU);
    float*  s_ml = reinterpret_cast<float*>(smraw + S_ML);
    float*  s_cu = reinterpret_cast<float*>(smraw + S_CU);
    float*  s_cl = reinterpret_cast<float*>(smraw + S_CL);
    float*  s_cs = reinterpret_cast<float*>(smraw + S_CS);
    float*  red  = reinterpret_cast<float*>(smraw + S_RED);
    float4* p4   = reinterpret_cast<float4*>(smraw + S_PART4);
    float*  p1   = reinterpret_cast<float*>(smraw + S_PART1);

    // ---- prologue: band-extract tm; off-diag pairs bf16, diag fp32 ----
    for (int r = tid; r < NK * NLOD; r += 512) {
        int k = r >> 7, ii = r & 127;
        long base = ((long)k * NLOD + ii) * NLOD;
        float m11[7], m12[7], m21[7], m22[7];
        #pragma unroll
        for (int d = 0; d < 7; d++) {
            int j = ii - 3 + d;
            if ((unsigned)j < (unsigned)NLOD) {
                m11[d] = __ldg(tm11 + base + j);
                m12[d] = __ldg(tm12 + base + j);
                m21[d] = __ldg(tm21 + base + j);
                m22[d] = __ldg(tm22 + base + j);
            } else {
                m11[d] = 0.f; m12[d] = 0.f; m21[d] = 0.f; m22[d] = 0.f;
            }
        }
        dg[k * NLOD + ii] = make_float4(m11[3], m12[3], m21[3], m22[3]);
        // plane 0 (g1): d0,d1   plane 1 (g2): d2,d4   plane 2 (g3): d5,d6
        od[(0 * NK + k) * NLOD + ii] = make_uint4(pk(m11[0], m12[0]), pk(m21[0], m22[0]),
                                                  pk(m11[1], m12[1]), pk(m21[1], m22[1]));
        od[(1 * NK + k) * NLOD + ii] = make_uint4(pk(m11[2], m12[2]), pk(m21[2], m22[2]),
                                                  pk(m11[4], m12[4]), pk(m21[4], m22[4]));
        od[(2 * NK + k) * NLOD + ii] = make_uint4(pk(m11[5], m12[5]), pk(m21[5], m22[5]),
                                                  pk(m11[6], m12[6]), pk(m21[6], m22[6]));
    }
    for (int idx = tid; idx < STATE_LEN; idx += 512) {
        s_mu[idx] = 0.f; s_ml[idx] = 0.f;
        s_cu[idx] = 0.f; s_cl[idx] = 0.f; s_cs[idx] = 0.f;
    }

    // per-thread constants
    const float bbl = __ldg(cb + (lane & 15));   // softmax bias for this lane's k

    float Wu[NK], Wl[NK];
    float tcur = 0.f, tclr = 0.f;
    float obs_r = 0.f, ov_r = 0.f;
    if (g == 0) {
        #pragma unroll
        for (int k = 0; k < NK; k++) {
            Wu[k] = __ldg(cw + i * NK + k);
            Wl[k] = __ldg(cw + (NLOD + i) * NK + k);
        }
        tcur = __ldg(tcu + i);
        tclr = __ldg(tcl + i);
        obs_r = __ldg(lobs  + ((long)b * NT) * NLOD + i);
        ov_r  = __ldg(ovars + ((long)b * NT) * NLOD + i);
        // seed partials with initial state (others zeroed below)
        p4[i] = make_float4(imean[(long)b * 2 * NLOD + i],
                            imean[(long)b * 2 * NLOD + NLOD + i],
                            icu[(long)b * NLOD + i] - tcur,
                            icl[(long)b * NLOD + i] - tclr);
        p1[i] = ics[(long)b * NLOD + i];
    } else {
        p4[g * NLOD + i] = make_float4(0.f, 0.f, 0.f, 0.f);
        p1[g * NLOD + i] = 0.f;
    }

    float* out_pm = out;
    float* out_cu = out + (long)NB * NT * 2 * NLOD;
    float* out_cl = out_cu + (long)NB * NT * NLOD;
    float* out_cs = out_cl + (long)NB * NT * NLOD;

    __syncthreads();

    for (int t = 0; t < NT; t++) {
        // ======== phase 1 (g0 only): combine partials, obs update, logits ====
        if (g == 0) {
            float4 q0 = p4[i], q1 = p4[NLOD + i], q2 = p4[2 * NLOD + i], q3 = p4[3 * NLOD + i];
            float pmU = ((q0.x + q1.x) + (q2.x + q3.x));
            float pmL = ((q0.y + q1.y) + (q2.y + q3.y));
            float cU  = ((q0.z + q1.z) + (q2.z + q3.z)) + tcur;
            float cL  = ((q0.w + q1.w) + (q2.w + q3.w)) + tclr;
            float cS  = ((p1[i] + p1[NLOD + i]) + (p1[2 * NLOD + i] + p1[3 * NLOD + i]));

            float denom = cU + ov_r;
            float rd    = 1.0f / denom;
            float qu    = cU * rd;
            float ql    = cS * rd;
            float res   = obs_r - pmU;
            float pu    = pmU + qu * res;
            float pl    = pmL + ql * res;
            float cf    = 1.0f - qu;
            float pcu   = cf * cU;
            float pcl   = cL - ql * cS;
            float pcs   = cf * cS;

            if (t + 1 < NT) {
                obs_r = __ldg(lobs  + ((long)b * NT + t + 1) * NLOD + i);
                ov_r  = __ldg(ovars + ((long)b * NT + t + 1) * NLOD + i);
            }

            s_mu[3 + i] = pu;  s_ml[3 + i] = pl;
            s_cu[3 + i] = pcu; s_cl[3 + i] = pcl; s_cs[3 + i] = pcs;

            long obase = (long)b * NT + t;
            out_pm[obase * 2 * NLOD + i]        = pu;
            out_pm[obase * 2 * NLOD + NLOD + i] = pl;
            out_cu[obase * NLOD + i] = pcu;
            out_cl[obase * NLOD + i] = pcl;
            out_cs[obase * NLOD + i] = pcs;

            // logits partial reduction (over this warp's 32 rows)
            float v[NK];
            #pragma unroll
            for (int k = 0; k < NK; k++) v[k] = fmaf(pu, Wu[k], pl * Wl[k]);
            #pragma unroll
            for (int k = 0; k < NK; k++) v[k] += __shfl_xor_sync(0xffffffffu, v[k], 16);
            RED_ROUND(8)
            RED_ROUND(4)
            RED_ROUND(2)
            RED_ROUND(1)
            if (lane < 16) red[lane * 4 + warp] = v[0];
        }
        __syncthreads();

        // ======== phase 2 (all): softmax (lane-parallel) + A-gen + matvec ====
        float aw;
        {
            const float4* red4 = reinterpret_cast<const float4*>(red);
            float4 rp = red4[lane & 15];
            float lg = bbl + ((rp.x + rp.y) + (rp.z + rp.w));
            float mx = lg;
            #pragma unroll
            for (int m = 8; m >= 1; m >>= 1)
                mx = fmaxf(mx, __shfl_xor_sync(0xffffffffu, mx, m));
            float w = __expf(lg - mx);
            float s = w;
            #pragma unroll
            for (int m = 8; m >= 1; m >>= 1)
                s += __shfl_xor_sync(0xffffffffu, s, m);
            aw = w * (1.0f / s);
        }

        float nmu = 0.f, nml = 0.f, ncu = 0.f, ncl = 0.f, ncs = 0.f;

        if (g == 0) {
            // diag d3, fp32
            float D11 = 0.f, D12 = 0.f, D21 = 0.f, D22 = 0.f;
            #pragma unroll
            for (int k = 0; k < NK; k++) {
                float4 gv = dg[k * NLOD + i];
                float  a  = __shfl_sync(0xffffffffu, aw, k);
                D11 = fmaf(a, gv.x, D11);
                D12 = fmaf(a, gv.y, D12);
                D21 = fmaf(a, gv.z, D21);
                D22 = fmaf(a, gv.w, D22);
            }
            BAND_ACC(3, D11 + 1.0f, D12, D21, D22 + 1.0f)
        } else {
            const uint4* plane = od + (g - 1) * NK * NLOD + i;
            unsigned long long P0 = 0ull, Q0 = 0ull, P1 = 0ull, Q1 = 0ull;
            #pragma unroll
            for (int k = 0; k < NK; k++) {
                uint4 v = plane[k * NLOD];
                unsigned long long a2 = dup2(__shfl_sync(0xffffffffu, aw, k));
                ffma2(P0, bf2f2(v.x), a2);
                ffma2(Q0, bf2f2(v.y), a2);
                ffma2(P1, bf2f2(v.z), a2);
                ffma2(Q1, bf2f2(v.w), a2);
            }
            float a11, a12, a21, a22;
            if (g == 1) {
                unpk2(P0, a11, a12); unpk2(Q0, a21, a22);
                BAND_ACC(0, a11, a12, a21, a22)
                unpk2(P1, a11, a12); unpk2(Q1, a21, a22);
                BAND_ACC(1, a11, a12, a21, a22)
            } else if (g == 2) {
                unpk2(P0, a11, a12); unpk2(Q0, a21, a22);
                BAND_ACC(2, a11, a12, a21, a22)
                unpk2(P1, a11, a12); unpk2(Q1, a21, a22);
                BAND_ACC(4, a11, a12, a21, a22)
            } else {
                unpk2(P0, a11, a12); unpk2(Q0, a21, a22);
                BAND_ACC(5, a11, a12, a21, a22)
                unpk2(P1, a11, a12); unpk2(Q1, a21, a22);
                BAND_ACC(6, a11, a12, a21, a22)
            }
        }

        p4[g * NLOD + i] = make_float4(nmu, nml, ncu, ncl);
        p1[g * NLOD + i] = ncs;
        __syncthreads();
    }
}

extern "C" void kernel_launch(void* const* d_in, const int* in_sizes, int n_in,
                              void* d_out, int out_size)
{
    (void)in_sizes; (void)n_in; (void)out_size;
    const float* lobs  = (const float*)d_in[0];
    const float* ovars = (const float*)d_in[1];
    const float* imean = (const float*)d_in[2];
    const float* icu   = (const float*)d_in[3];
    const float* icl   = (const float*)d_in[4];
    const float* ics   = (const float*)d_in[5];
    const float* tm11  = (const float*)d_in[6];
    const float* tm12  = (const float*)d_in[7];
    const float* tm21  = (const float*)d_in[8];
    const float* tm22  = (const float*)d_in[9];
    const float* cw    = (const float*)d_in[10];
    const float* cb    = (const float*)d_in[11];
    const float* tcu   = (const float*)d_in[12];
    const float* tcl   = (const float*)d_in[13];
    float* out = (float*)d_out;

    cudaFuncSetAttribute(rkn_kernel,
                         cudaFuncAttributeMaxDynamicSharedMemorySize, SMEM_BYTES);

    rkn_kernel<<<NB, 512, SMEM_BYTES>>>(lobs, ovars, imean, icu, icl, ics,
                                        tm11, tm12, tm21, tm22,
                                        cw, cb, tcu, tcl, out);
}

// round 4
// speedup vs baseline: 1.0490x; 1.0490x over previous
#include <cuda_runtime.h>
#include <cuda_bf16.h>

// RKN scan R4: tm tables register-resident (bf16 packed, 4-way diagonal split),
// disjoint per-group t-loops synced via named barrier, diag plane in smem fp32.

#define NB   128
#define NT   128
#define NLOD 128
#define NK   16

__device__ __forceinline__ unsigned int pk(float a, float b) {
    __nv_bfloat162 t = __floats2bfloat162_rn(a, b);
    return reinterpret_cast<unsigned int&>(t);
}
// acc(f32x2) += { exact lo: p<<16 , approx hi: raw p (garbage low mantissa) } * {a,a}
__device__ __forceinline__ void pair_fma(unsigned long long& acc,
                                         unsigned int p, unsigned long long a2) {
    asm("{\n\t.reg .b32 lo;\n\t.reg .b64 v;\n\t"
        "shl.b32 lo, %1, 16;\n\t"
        "mov.b64 v, {lo, %1};\n\t"
        "fma.rn.f32x2 %0, v, %2, %0;\n\t}"
        : "+l"(acc) : "r"(p), "l"(a2));
}
__device__ __forceinline__ unsigned long long dup2(float a) {
    unsigned long long r;
    asm("mov.b64 %0, {%1, %1};" : "=l"(r) : "f"(a));
    return r;
}
__device__ __forceinline__ void unpk2(unsigned long long r, float& x, float& y) {
    asm("mov.b64 {%0, %1}, %2;" : "=f"(x), "=f"(y) : "l"(r));
}
__device__ __forceinline__ void barrier512() {
    asm volatile("bar.sync 0, 512;" ::: "memory");
}

#define RED_ROUND(m)                                                          \
  _Pragma("unroll")                                                           \
  for (int k = 0; k < (m); k++) {                                             \
    float a_ = v[k], c_ = v[k + (m)];                                         \
    bool  hi_ = (lane & (m)) != 0;                                            \
    float keep_ = hi_ ? c_ : a_;                                              \
    float send_ = hi_ ? a_ : c_;                                              \
    v[k] = keep_ + __shfl_xor_sync(0xffffffffu, send_, (m));                  \
  }

#define BAND_ACC(d, a11, a12, a21, a22)                                       \
  {                                                                           \
    int j_ = i + (d);                                                         \
    float muj = s_mu[j_], mlj = s_ml[j_];                                     \
    float cuj = s_cu[j_], clj = s_cl[j_], csj = s_cs[j_];                     \
    nmu = fmaf((a11), muj, nmu); nmu = fmaf((a12), mlj, nmu);                 \
    nml = fmaf((a21), muj, nml); nml = fmaf((a22), mlj, nml);                 \
    ncu = fmaf((a11) * (a11), cuj, ncu);                                      \
    ncu = fmaf(2.0f * (a11) * (a12), csj, ncu);                               \
    ncu = fmaf((a12) * (a12), clj, ncu);                                      \
    ncl = fmaf((a21) * (a21), cuj, ncl);                                      \
    ncl = fmaf(2.0f * (a21) * (a22), csj, ncl);                               \
    ncl = fmaf((a22) * (a22), clj, ncl);                                      \
    ncs = fmaf((a21) * (a11), cuj, ncs);                                      \
    ncs = fmaf(fmaf((a22), (a11), (a21) * (a12)), csj, ncs);                  \
    ncs = fmaf((a22) * (a12), clj, ncs);                                      \
  }

#define SOFTMAX_AW(aw)                                                        \
  {                                                                           \
    const float4* red4_ = reinterpret_cast<const float4*>(red);               \
    float4 rp_ = red4_[lane & 15];                                            \
    float lg_ = bbl + ((rp_.x + rp_.y) + (rp_.z + rp_.w));                    \
    float mx_ = lg_;                                                          \
    _Pragma("unroll")                                                         \
    for (int m_ = 8; m_ >= 1; m_ >>= 1)                                       \
      mx_ = fmaxf(mx_, __shfl_xor_sync(0xffffffffu, mx_, m_));                \
    float w_ = __expf(lg_ - mx_);                                             \
    float s_ = w_;                                                            \
    _Pragma("unroll")                                                         \
    for (int m_ = 8; m_ >= 1; m_ >>= 1)                                       \
      s_ += __shfl_xor_sync(0xffffffffu, s_, m_);                             \
    (aw) = w_ * (1.0f / s_);                                                  \
  }

__global__ void __launch_bounds__(512, 1)
rkn_kernel(const float* __restrict__ lobs,   // (B,T,LOD)
           const float* __restrict__ ovars,  // (B,T,LOD)
           const float* __restrict__ imean,  // (B,2*LOD)
           const float* __restrict__ icu,
           const float* __restrict__ icl,
           const float* __restrict__ ics,
           const float* __restrict__ tm11,   // (K,LOD,LOD)
           const float* __restrict__ tm12,
           const float* __restrict__ tm21,
           const float* __restrict__ tm22,
           const float* __restrict__ cw,     // (2*LOD, K)
           const float* __restrict__ cb,     // (K,)
           const float* __restrict__ tcu,
           const float* __restrict__ tcl,
           float* __restrict__ out)
{
    __shared__ float4 dg[NK * NLOD];            // fp32 diagonal plane (32 KB)
    __shared__ float  s_mu[136], s_ml[136], s_cu[136], s_cl[136], s_cs[136];
    __shared__ float  red[64];                  // 16 k x 4 warp partial logits
    __shared__ float4 p4[3 * NLOD];             // g1..g3 partials (nmu,nml,ncu,ncl)
    __shared__ float  p1[3 * NLOD];             // g1..g3 partial ncs

    const int b    = blockIdx.x;
    const int tid  = threadIdx.x;
    const int lane = tid & 31;
    const int warp = tid >> 5;
    const int i    = tid & 127;   // row
    const int g    = tid >> 7;    // group 0..3

    // ---- prologue (convergent) ----
    for (int r = tid; r < NK * NLOD; r += 512) {
        int k = r >> 7, ii = r & 127;
        long base = ((long)k * NLOD + ii) * NLOD + ii;
        dg[r] = make_float4(__ldg(tm11 + base), __ldg(tm12 + base),
                            __ldg(tm21 + base), __ldg(tm22 + base));
    }
    for (int idx = tid; idx < 136; idx += 512) {
        s_mu[idx] = 0.f; s_ml[idx] = 0.f;
        s_cu[idx] = 0.f; s_cl[idx] = 0.f; s_cs[idx] = 0.f;
    }
    if (g > 0) { p4[(g - 1) * NLOD + i] = make_float4(0.f, 0.f, 0.f, 0.f);
                 p1[(g - 1) * NLOD + i] = 0.f; }

    const float bbl = __ldg(cb + (lane & 15));

    float* out_pm = out;
    float* out_cu = out + (long)NB * NT * 2 * NLOD;
    float* out_cl = out_cu + (long)NB * NT * NLOD;
    float* out_cs = out_cl + (long)NB * NT * NLOD;

    __syncthreads();   // prologue visibility (still convergent here)

    if (g == 0) {
        // ---- g0: serial head + fp32 diagonal (d=3) ----
        float Wu[NK], Wl[NK];
        #pragma unroll
        for (int k = 0; k < NK; k++) {
            Wu[k] = __ldg(cw + i * NK + k);
            Wl[k] = __ldg(cw + (NLOD + i) * NK + k);
        }
        const float tcur = __ldg(tcu + i);
        const float tclr = __ldg(tcl + i);
        // own carry partial in registers; tcur/tclr pre-subtracted (combine re-adds)
        float nmu = imean[(long)b * 2 * NLOD + i];
        float nml = imean[(long)b * 2 * NLOD + NLOD + i];
        float ncu = icu[(long)b * NLOD + i] - tcur;
        float ncl = icl[(long)b * NLOD + i] - tclr;
        float ncs = ics[(long)b * NLOD + i];
        float obs_r = __ldg(lobs  + ((long)b * NT) * NLOD + i);
        float ov_r  = __ldg(ovars + ((long)b * NT) * NLOD + i);

        for (int t = 0; t < NT; t++) {
            // ---- phase 1: combine partials -> posterior -> logits ----
            float4 q1 = p4[i], q2 = p4[NLOD + i], q3 = p4[2 * NLOD + i];
            float pmU = nmu + ((q1.x + q2.x) + q3.x);
            float pmL = nml + ((q1.y + q2.y) + q3.y);
            float cU  = (ncu + ((q1.z + q2.z) + q3.z)) + tcur;
            float cL  = (ncl + ((q1.w + q2.w) + q3.w)) + tclr;
            float cS  = ncs + ((p1[i] + p1[NLOD + i]) + p1[2 * NLOD + i]);

            float denom = cU + ov_r;
            float rd    = 1.0f / denom;
            float qu    = cU * rd;
            float ql    = cS * rd;
            float res   = obs_r - pmU;
            float pu    = pmU + qu * res;
            float pl    = pmL + ql * res;
            float cf    = 1.0f - qu;
            float pcu   = cf * cU;
            float pcl   = cL - ql * cS;
            float pcs   = cf * cS;

            if (t + 1 < NT) {
                obs_r = __ldg(lobs  + ((long)b * NT + t + 1) * NLOD + i);
                ov_r  = __ldg(ovars + ((long)b * NT + t + 1) * NLOD + i);
            }

            s_mu[3 + i] = pu;  s_ml[3 + i] = pl;
            s_cu[3 + i] = pcu; s_cl[3 + i] = pcl; s_cs[3 + i] = pcs;

            long obase = (long)b * NT + t;
            out_pm[obase * 2 * NLOD + i]        = pu;
            out_pm[obase * 2 * NLOD + NLOD + i] = pl;
            out_cu[obase * NLOD + i] = pcu;
            out_cl[obase * NLOD + i] = pcl;
            out_cs[obase * NLOD + i] = pcs;

            float v[NK];
            #pragma unroll
            for (int k = 0; k < NK; k++) v[k] = fmaf(pu, Wu[k], pl * Wl[k]);
            #pragma unroll
            for (int k = 0; k < NK; k++) v[k] += __shfl_xor_sync(0xffffffffu, v[k], 16);
            RED_ROUND(8)
            RED_ROUND(4)
            RED_ROUND(2)
            RED_ROUND(1)
            if (lane < 16) red[lane * 4 + warp] = v[0];
            barrier512();   // B1

            // ---- phase 2: softmax + diagonal A + matvec (result kept in regs) ----
            float aw;
            SOFTMAX_AW(aw)

            float D11 = 0.f, D12 = 0.f, D21 = 0.f, D22 = 0.f;
            #pragma unroll
            for (int k = 0; k < NK; k++) {
                float4 gv = dg[k * NLOD + i];
                float  a  = __shfl_sync(0xffffffffu, aw, k);
                D11 = fmaf(a, gv.x, D11);
                D12 = fmaf(a, gv.y, D12);
                D21 = fmaf(a, gv.z, D21);
                D22 = fmaf(a, gv.w, D22);
            }
            nmu = 0.f; nml = 0.f; ncu = 0.f; ncl = 0.f; ncs = 0.f;
            BAND_ACC(3, D11 + 1.0f, D12, D21, D22 + 1.0f)
            barrier512();   // B2
        }
    } else {
        // ---- g1..g3: register-resident bf16-packed off-diagonal planes ----
        const int da = (g == 1) ? 0 : (g == 2) ? 2 : 5;
        const int db = (g == 1) ? 1 : (g == 2) ? 4 : 6;
        const int ja = i - 3 + da, jb = i - 3 + db;
        const bool va = (unsigned)ja < (unsigned)NLOD;
        const bool vb = (unsigned)jb < (unsigned)NLOD;

        uint4 R[NK];
        #pragma unroll
        for (int k = 0; k < NK; k++) {
            long base = ((long)k * NLOD + i) * NLOD;
            float a11 = 0.f, a12 = 0.f, a21 = 0.f, a22 = 0.f;
            float c11 = 0.f, c12 = 0.f, c21 = 0.f, c22 = 0.f;
            if (va) {
                a11 = __ldg(tm11 + base + ja); a12 = __ldg(tm12 + base + ja);
                a21 = __ldg(tm21 + base + ja); a22 = __ldg(tm22 + base + ja);
            }
            if (vb) {
                c11 = __ldg(tm11 + base + jb); c12 = __ldg(tm12 + base + jb);
                c21 = __ldg(tm21 + base + jb); c22 = __ldg(tm22 + base + jb);
            }
            R[k] = make_uint4(pk(a11, a12), pk(a21, a22),
                              pk(c11, c12), pk(c21, c22));
        }

        for (int t = 0; t < NT; t++) {
            barrier512();   // B1

            float aw;
            SOFTMAX_AW(aw)

            unsigned long long Pa = 0ull, Qa = 0ull, Pb = 0ull, Qb = 0ull;
            #pragma unroll
            for (int k = 0; k < NK; k++) {
                unsigned long long a2 = dup2(__shfl_sync(0xffffffffu, aw, k));
                uint4 r = R[k];
                pair_fma(Pa, r.x, a2);
                pair_fma(Qa, r.y, a2);
                pair_fma(Pb, r.z, a2);
                pair_fma(Qb, r.w, a2);
            }

            float nmu = 0.f, nml = 0.f, ncu = 0.f, ncl = 0.f, ncs = 0.f;
            float a11, a12, a21, a22;
            unpk2(Pa, a11, a12); unpk2(Qa, a21, a22);
            BAND_ACC(da, a11, a12, a21, a22)
            unpk2(Pb, a11, a12); unpk2(Qb, a21, a22);
            BAND_ACC(db, a11, a12, a21, a22)

            p4[(g - 1) * NLOD + i] = make_float4(nmu, nml, ncu, ncl);
            p1[(g - 1) * NLOD + i] = ncs;
            barrier512();   // B2
        }
    }
}

extern "C" void kernel_launch(void* const* d_in, const int* in_sizes, int n_in,
                              void* d_out, int out_size)
{
    (void)in_sizes; (void)n_in; (void)out_size;
    const float* lobs  = (const float*)d_in[0];
    const float* ovars = (const float*)d_in[1];
    const float* imean = (const float*)d_in[2];
    const float* icu   = (const float*)d_in[3];
    const float* icl   = (const float*)d_in[4];
    const float* ics   = (const float*)d_in[5];
    const float* tm11  = (const float*)d_in[6];
    const float* tm12  = (const float*)d_in[7];
    const float* tm21  = (const float*)d_in[8];
    const float* tm22  = (const float*)d_in[9];
    const float* cw    = (const float*)d_in[10];
    const float* cb    = (const float*)d_in[11];
    const float* tcu   = (const float*)d_in[12];
    const float* tcl   = (const float*)d_in[13];
    float* out = (float*)d_out;

    rkn_kernel<<<NB, 512>>>(lobs, ovars, imean, icu, icl, ics,
                            tm11, tm12, tm21, tm22,
                            cw, cb, tcu, tcl, out);
}